// round 5
// baseline (speedup 1.0000x reference)
#include <cuda_runtime.h>
#include <cuda_bf16.h>
#include <stdint.h>
#include <math.h>

// ---------------------------------------------------------------------------
// Mixtral sparse MoE block, GB300 (sm_103a)
// B=2, S=1024 -> T=2048 tokens, H=1024, E=8, F=2816, TOP_K=2
// Outputs (concatenated fp32): final_hidden_states [2,1024,1024], router_logits [2048,8]
// ---------------------------------------------------------------------------

constexpr int T = 2048;
constexpr int H = 1024;
constexpr int E = 8;
constexpr int F = 2816;
constexpr int AMAX = 2 * T;          // total assignments (top-2)
constexpr int APAD = AMAX + 128;     // pad so last tile can over-read safely

// Scratch (static __device__ globals: allocation-free rule)
__device__ float g_act[(size_t)APAD * F];   // post-SwiGLU activations per slot
__device__ float g_y[(size_t)APAD * H];     // per-slot down-proj results
__device__ int   g_cnt[E];
__device__ int   g_off[E];
__device__ int   g_cur[E];
__device__ int   g_top_e[T * 2];
__device__ float g_top_w[T * 2];
__device__ int   g_assign_tok[AMAX];
__device__ float g_assign_w[AMAX];
__device__ int   g_tok2slot[T * 2];
__device__ float g_logits_dummy[T * E];     // fallback if out buffer lacks logits region

// ---------------------------------------------------------------------------
// tf32 helpers (legacy mma.sync path; tcgen05 port planned after profiling)
// ---------------------------------------------------------------------------
__device__ __forceinline__ uint32_t f2tf32(float f) {
    uint32_t u;
    asm("cvt.rna.tf32.f32 %0, %1;" : "=r"(u) : "f"(f));
    return u;
}

__device__ __forceinline__ void mma_tf32(float* c, const uint32_t* a, const uint32_t* b) {
    asm volatile(
        "mma.sync.aligned.m16n8k8.row.col.f32.tf32.tf32.f32 "
        "{%0,%1,%2,%3}, {%4,%5,%6,%7}, {%8,%9}, {%0,%1,%2,%3};\n"
        : "+f"(c[0]), "+f"(c[1]), "+f"(c[2]), "+f"(c[3])
        : "r"(a[0]), "r"(a[1]), "r"(a[2]), "r"(a[3]), "r"(b[0]), "r"(b[1]));
}

// ---------------------------------------------------------------------------
// 0) zero per-launch state (graph replays reuse the globals)
// ---------------------------------------------------------------------------
__global__ void zero_counts_kernel() {
    if (threadIdx.x < E) g_cnt[threadIdx.x] = 0;
}

// ---------------------------------------------------------------------------
// 1) Router: logits (fp32 exact), top-2, pairwise-softmax weights.
//    warp-per-token; gate_w (32KB) staged in smem.
// ---------------------------------------------------------------------------
__global__ __launch_bounds__(256) void router_kernel(
    const float* __restrict__ x, const float* __restrict__ gw,
    float* __restrict__ logits_out) {
    __shared__ float sgw[E * H];
    int tid = threadIdx.x;
    for (int i = tid; i < E * H; i += 256) sgw[i] = gw[i];
    __syncthreads();

    int warp = tid >> 5, lane = tid & 31;
    int t = blockIdx.x * 8 + warp;

    float xr[32];
    const float* xp = x + (size_t)t * H;
#pragma unroll
    for (int i = 0; i < 32; i++) xr[i] = xp[i * 32 + lane];

    float l[E];
#pragma unroll
    for (int e = 0; e < E; e++) {
        float acc = 0.f;
        const float* g = sgw + e * H;
#pragma unroll
        for (int i = 0; i < 32; i++) acc += xr[i] * g[i * 32 + lane];
#pragma unroll
        for (int o = 16; o > 0; o >>= 1) acc += __shfl_xor_sync(0xffffffffu, acc, o);
        l[e] = acc;
    }

    if (lane == 0) {
#pragma unroll
        for (int e = 0; e < E; e++) logits_out[(size_t)t * E + e] = l[e];
        // top-2 (first occurrence wins ties, matching jax top_k)
        int e0 = 0; float b0 = l[0];
#pragma unroll
        for (int e = 1; e < E; e++) if (l[e] > b0) { b0 = l[e]; e0 = e; }
        int e1 = (e0 == 0) ? 1 : 0; float b1 = l[e1];
#pragma unroll
        for (int e = 0; e < E; e++)
            if (e != e0 && l[e] > b1) { b1 = l[e]; e1 = e; }
        // renormalized top-2 softmax == pairwise softmax of top-2 logits
        float p = expf(b1 - b0);
        float inv = 1.f / (1.f + p);
        g_top_e[2 * t]     = e0; g_top_w[2 * t]     = inv;
        g_top_e[2 * t + 1] = e1; g_top_w[2 * t + 1] = p * inv;
        atomicAdd(&g_cnt[e0], 1);
        atomicAdd(&g_cnt[e1], 1);
    }
}

// ---------------------------------------------------------------------------
// 2) tiny exclusive scan (E=8)
// ---------------------------------------------------------------------------
__global__ void scan_kernel() {
    int off = 0;
    for (int e = 0; e < E; e++) { g_off[e] = off; g_cur[e] = off; off += g_cnt[e]; }
}

// ---------------------------------------------------------------------------
// 3) slot assignment (contiguous per-expert segments)
// ---------------------------------------------------------------------------
__global__ void assign_kernel() {
    int t = blockIdx.x * blockDim.x + threadIdx.x;
    if (t >= T) return;
#pragma unroll
    for (int k = 0; k < 2; k++) {
        int e = g_top_e[2 * t + k];
        int slot = atomicAdd(&g_cur[e], 1);
        g_assign_tok[slot] = t;
        g_assign_w[slot]   = g_top_w[2 * t + k];
        g_tok2slot[2 * t + k] = slot;
    }
}

// ---------------------------------------------------------------------------
// 4) GEMM1: for each expert segment, act = silu(X@w1) * (X@w3) * route_w
//    Block tile 128(M) x 64(N), K-tile 32. Dual-B (w1,w3) shares the gathered
//    A tile. 8 warps = 4(M) x 2(N), warp tile 32x32 per matrix.
// ---------------------------------------------------------------------------
__global__ __launch_bounds__(256) void gemm1_kernel(
    const float* __restrict__ x,
    const float* __restrict__ w1,
    const float* __restrict__ w3) {
    const int e = blockIdx.z;
    const int cnt = g_cnt[e];
    const int mt = blockIdx.y;
    if (mt * 128 >= cnt) return;
    const int off = g_off[e];
    const int n0 = blockIdx.x * 64;

    __shared__ uint32_t As[128][36];   // +4 pad: conflict-free frag loads
    __shared__ uint32_t B1s[32][72];   // +8 pad
    __shared__ uint32_t B3s[32][72];
    __shared__ int   stok[128];
    __shared__ float swt[128];

    const int tid = threadIdx.x;
    if (tid < 128) {
        int r = mt * 128 + tid;
        if (r < cnt) { stok[tid] = g_assign_tok[off + r]; swt[tid] = g_assign_w[off + r]; }
        else         { stok[tid] = 0;                     swt[tid] = 0.f; }
    }
    __syncthreads();

    const int lane = tid & 31, warp = tid >> 5;
    const int wm = warp >> 1;   // 0..3
    const int wn = warp & 1;    // 0..1
    const int lr = lane >> 2;   // groupID
    const int lc = lane & 3;    // threadID_in_group

    float accG[2][4][4];
    float accU[2][4][4];
#pragma unroll
    for (int i = 0; i < 2; i++)
#pragma unroll
        for (int j = 0; j < 4; j++)
#pragma unroll
            for (int c = 0; c < 4; c++) { accG[i][j][c] = 0.f; accU[i][j][c] = 0.f; }

    const size_t wbase = (size_t)e * H * F + n0;

    for (int k0 = 0; k0 < H; k0 += 32) {
        // A: 128x32 fp32 gathered rows -> tf32 in smem
#pragma unroll
        for (int v = 0; v < 4; v++) {
            int idx = tid + v * 256;
            int row = idx >> 3;
            int c4 = (idx & 7) << 2;
            const float4 f = *(const float4*)(x + (size_t)stok[row] * H + k0 + c4);
            *(uint4*)&As[row][c4] =
                make_uint4(f2tf32(f.x), f2tf32(f.y), f2tf32(f.z), f2tf32(f.w));
        }
        // B1/B3: 32x64 tiles
#pragma unroll
        for (int v = 0; v < 2; v++) {
            int idx = tid + v * 256;
            int row = idx >> 4;           // 0..31
            int c4 = (idx & 15) << 2;     // 0..60
            size_t gidx = wbase + (size_t)(k0 + row) * F + c4;
            float4 f1 = *(const float4*)(w1 + gidx);
            *(uint4*)&B1s[row][c4] =
                make_uint4(f2tf32(f1.x), f2tf32(f1.y), f2tf32(f1.z), f2tf32(f1.w));
            float4 f3 = *(const float4*)(w3 + gidx);
            *(uint4*)&B3s[row][c4] =
                make_uint4(f2tf32(f3.x), f2tf32(f3.y), f2tf32(f3.z), f2tf32(f3.w));
        }
        __syncthreads();

#pragma unroll
        for (int kk = 0; kk < 4; kk++) {
            uint32_t a[2][4];
#pragma unroll
            for (int mi = 0; mi < 2; mi++) {
                int r0 = wm * 32 + mi * 16 + lr;
                int cA = kk * 8 + lc;
                a[mi][0] = As[r0][cA];
                a[mi][1] = As[r0 + 8][cA];
                a[mi][2] = As[r0][cA + 4];
                a[mi][3] = As[r0 + 8][cA + 4];
            }
#pragma unroll
            for (int ni = 0; ni < 4; ni++) {
                int col = wn * 32 + ni * 8 + lr;
                int rB = kk * 8 + lc;
                uint32_t b1[2] = { B1s[rB][col], B1s[rB + 4][col] };
                uint32_t b3[2] = { B3s[rB][col], B3s[rB + 4][col] };
#pragma unroll
                for (int mi = 0; mi < 2; mi++) {
                    mma_tf32(accG[mi][ni], a[mi], b1);
                    mma_tf32(accU[mi][ni], a[mi], b3);
                }
            }
        }
        __syncthreads();
    }

    // Epilogue: act = route_w * u * silu(g)
#pragma unroll
    for (int mi = 0; mi < 2; mi++) {
#pragma unroll
        for (int half = 0; half < 2; half++) {
            int row = wm * 32 + mi * 16 + lr + half * 8;
            int grow = mt * 128 + row;
            if (grow < cnt) {
                float w = swt[row];
                float* dst = g_act + (size_t)(off + grow) * F + n0;
#pragma unroll
                for (int ni = 0; ni < 4; ni++) {
                    int col = wn * 32 + ni * 8 + lc * 2;
                    float gg = accG[mi][ni][half * 2 + 0];
                    float uu = accU[mi][ni][half * 2 + 0];
                    float a0 = w * uu * (gg / (1.f + expf(-gg)));
                    gg = accG[mi][ni][half * 2 + 1];
                    uu = accU[mi][ni][half * 2 + 1];
                    float a1 = w * uu * (gg / (1.f + expf(-gg)));
                    *(float2*)(dst + col) = make_float2(a0, a1);
                }
            }
        }
    }
}

// ---------------------------------------------------------------------------
// 5) GEMM2: y = act @ w2[e]   (K = 2816, N = 1024), contiguous A rows
// ---------------------------------------------------------------------------
__global__ __launch_bounds__(256) void gemm2_kernel(const float* __restrict__ w2) {
    const int e = blockIdx.z;
    const int cnt = g_cnt[e];
    const int mt = blockIdx.y;
    if (mt * 128 >= cnt) return;
    const int off = g_off[e];
    const int n0 = blockIdx.x * 64;

    __shared__ uint32_t As[128][36];
    __shared__ uint32_t Bs[32][72];

    const int tid = threadIdx.x;
    const int lane = tid & 31, warp = tid >> 5;
    const int wm = warp >> 1, wn = warp & 1;
    const int lr = lane >> 2, lc = lane & 3;

    float acc[2][4][4];
#pragma unroll
    for (int i = 0; i < 2; i++)
#pragma unroll
        for (int j = 0; j < 4; j++)
#pragma unroll
            for (int c = 0; c < 4; c++) acc[i][j][c] = 0.f;

    const float* Abase = g_act + (size_t)(off + mt * 128) * F;
    const size_t w2base = (size_t)e * F * H + n0;

    for (int k0 = 0; k0 < F; k0 += 32) {
#pragma unroll
        for (int v = 0; v < 4; v++) {
            int idx = tid + v * 256;
            int row = idx >> 3;
            int c4 = (idx & 7) << 2;
            const float4 f = *(const float4*)(Abase + (size_t)row * F + k0 + c4);
            *(uint4*)&As[row][c4] =
                make_uint4(f2tf32(f.x), f2tf32(f.y), f2tf32(f.z), f2tf32(f.w));
        }
#pragma unroll
        for (int v = 0; v < 2; v++) {
            int idx = tid + v * 256;
            int row = idx >> 4;
            int c4 = (idx & 15) << 2;
            const float4 f = *(const float4*)(w2 + w2base + (size_t)(k0 + row) * H + c4);
            *(uint4*)&Bs[row][c4] =
                make_uint4(f2tf32(f.x), f2tf32(f.y), f2tf32(f.z), f2tf32(f.w));
        }
        __syncthreads();

#pragma unroll
        for (int kk = 0; kk < 4; kk++) {
            uint32_t a[2][4];
#pragma unroll
            for (int mi = 0; mi < 2; mi++) {
                int r0 = wm * 32 + mi * 16 + lr;
                int cA = kk * 8 + lc;
                a[mi][0] = As[r0][cA];
                a[mi][1] = As[r0 + 8][cA];
                a[mi][2] = As[r0][cA + 4];
                a[mi][3] = As[r0 + 8][cA + 4];
            }
#pragma unroll
            for (int ni = 0; ni < 4; ni++) {
                int col = wn * 32 + ni * 8 + lr;
                int rB = kk * 8 + lc;
                uint32_t b[2] = { Bs[rB][col], Bs[rB + 4][col] };
#pragma unroll
                for (int mi = 0; mi < 2; mi++) mma_tf32(acc[mi][ni], a[mi], b);
            }
        }
        __syncthreads();
    }

#pragma unroll
    for (int mi = 0; mi < 2; mi++) {
#pragma unroll
        for (int half = 0; half < 2; half++) {
            int row = wm * 32 + mi * 16 + lr + half * 8;
            int grow = mt * 128 + row;
            if (grow < cnt) {
                float* dst = g_y + (size_t)(off + grow) * H + n0;
#pragma unroll
                for (int ni = 0; ni < 4; ni++) {
                    int col = wn * 32 + ni * 8 + lc * 2;
                    *(float2*)(dst + col) =
                        make_float2(acc[mi][ni][half * 2 + 0], acc[mi][ni][half * 2 + 1]);
                }
            }
        }
    }
}

// ---------------------------------------------------------------------------
// 6) combine: out[t] = y[slot0(t)] + y[slot1(t)]
// ---------------------------------------------------------------------------
__global__ void combine_kernel(float* __restrict__ out) {
    int t = blockIdx.x;
    int s0 = g_tok2slot[2 * t];
    int s1 = g_tok2slot[2 * t + 1];
    const float4* y0 = (const float4*)(g_y + (size_t)s0 * H);
    const float4* y1 = (const float4*)(g_y + (size_t)s1 * H);
    float4 a = y0[threadIdx.x];
    float4 b = y1[threadIdx.x];
    ((float4*)(out + (size_t)t * H))[threadIdx.x] =
        make_float4(a.x + b.x, a.y + b.y, a.z + b.z, a.w + b.w);
}

// ---------------------------------------------------------------------------
extern "C" void kernel_launch(void* const* d_in, const int* in_sizes, int n_in,
                              void* d_out, int out_size) {
    const float* x  = (const float*)d_in[0];   // hidden_states [2,1024,1024]
    const float* gw = (const float*)d_in[1];   // gate_w [8,1024]
    const float* w1 = (const float*)d_in[2];   // [8,1024,2816]
    const float* w3 = (const float*)d_in[3];   // [8,1024,2816]
    const float* w2 = (const float*)d_in[4];   // [8,2816,1024]
    float* out = (float*)d_out;

    // router_logits live after final_hidden_states in the concatenated output
    float* logits;
    if (out_size >= T * H + T * E) {
        logits = out + (size_t)T * H;
    } else {
        cudaGetSymbolAddress((void**)&logits, g_logits_dummy);
    }

    zero_counts_kernel<<<1, 32>>>();
    router_kernel<<<T / 8, 256>>>(x, gw, logits);
    scan_kernel<<<1, 1>>>();
    assign_kernel<<<(T + 255) / 256, 256>>>();
    gemm1_kernel<<<dim3(F / 64, 16, E), 256>>>(x, w1, w3);
    gemm2_kernel<<<dim3(H / 64, 16, E), 256>>>(w2);
    combine_kernel<<<T, 256>>>(out);
}